// round 5
// baseline (speedup 1.0000x reference)
#include <cuda_runtime.h>
#include <math.h>
#include <stdint.h>

#define BB 2
#define SS 1024
#define DMODEL 1024
#define HH 16
#define DD 64
#define PP 512               // 2*SPAN
#define BH (BB*HH)
#define INV_SCALE 0.07216878364870323f   // 1/sqrt(192)
#define STAGES 3

// ---------------- scratch (static device memory; no allocs allowed) ----------
__device__ float g_Q[BH*SS*DD];      // [bh][s][64]
__device__ float g_K[BH*SS*DD];
__device__ float g_V[BH*SS*DD];
__device__ float g_Vt[BH*DD*SS];     // [bh][64][s]
__device__ float g_posK[HH*PP*DD];   // [h][p][64]
__device__ float g_posQ[HH*PP*DD];
__device__ float g_Wt[4u*DMODEL*DMODEL]; // Wq^T, Wk^T, Wv^T, Wo^T
__device__ float g_C2P[(size_t)BH*SS*PP];
__device__ float g_P2C[(size_t)BH*SS*PP];
__device__ float g_ctx[BB*SS*DMODEL];
__device__ float g_H[BB*SS*DMODEL];
__device__ int   g_idx[2047];

// ---------------- idx table: clip(bucket(delta)+256, 0, 511) -----------------
__global__ void build_idx_kernel() {
    int t = blockIdx.x * blockDim.x + threadIdx.x;
    if (t >= 2047) return;
    int rel = t - 1023;
    int bucket;
    if (rel > -128 && rel < 128) {
        bucket = rel;
    } else {
        double abs_pos = fabs((double)rel);
        if (abs_pos <= 128.0) {
            bucket = rel;
        } else {
            int sgn = (rel > 0) - (rel < 0);
            double lp = ceil(log(abs_pos / 128.0) / log(511.0 / 128.0) * 127.0) + 128.0;
            bucket = (int)lp * sgn;
        }
    }
    int i1 = bucket + 256;
    i1 = i1 < 0 ? 0 : (i1 > 511 ? 511 : i1);
    g_idx[t] = i1;
}

__device__ __forceinline__ float to_tf32(float x) {
    float y;
    asm("cvt.rna.tf32.f32 %0, %1;" : "=f"(y) : "f"(x));
    return y;
}

__device__ __forceinline__ void mma_tf32(float (&d)[4],
                                         uint32_t a0, uint32_t a1, uint32_t a2, uint32_t a3,
                                         uint32_t b0, uint32_t b1) {
    asm volatile(
        "mma.sync.aligned.m16n8k8.row.col.f32.tf32.tf32.f32 "
        "{%0,%1,%2,%3}, {%4,%5,%6,%7}, {%8,%9}, {%0,%1,%2,%3};\n"
        : "+f"(d[0]), "+f"(d[1]), "+f"(d[2]), "+f"(d[3])
        : "r"(a0), "r"(a1), "r"(a2), "r"(a3), "r"(b0), "r"(b1));
}

__device__ __forceinline__ void cpa16(uint32_t s, const float* g) {
    asm volatile("cp.async.cg.shared.global [%0], [%1], 16;\n" :: "r"(s), "l"(g));
}
#define CP_COMMIT() asm volatile("cp.async.commit_group;\n" ::: "memory")
#define CP_WAIT1()  asm volatile("cp.async.wait_group 1;\n" ::: "memory")
#define CP_WAIT0()  asm volatile("cp.async.wait_group 0;\n" ::: "memory")

// ============================================================================
// NT tf32 GEMM, 3-stage cp.async pipeline, XOR-swizzled smem.
//   C[z] = A[z] (MxK row-major) @ B[z] (NxK row-major)^T + epilogue
// EPI 0: plain store   EPI 1: head-major scatter + bias (z selects B/bias/O)
// EPI 2: +bias+resid   EPI 5: c2p/p2c merged (z<32: A,B0->O0 ; z>=32: B1,B2->O1)
// ============================================================================
template<int BN, int EPI>
__global__ __launch_bounds__(256) void mm_nt(
    const float* __restrict__ A, int lda, long long sAz,
    const float* __restrict__ B0, const float* __restrict__ B1, const float* __restrict__ B2,
    int ldb, long long sBz, int bmod16,
    float* __restrict__ O0, float* __restrict__ O1, float* __restrict__ O2,
    int ldc, long long sCz, int K,
    const float* __restrict__ bias0, const float* __restrict__ bias1, const float* __restrict__ bias2,
    const float* __restrict__ resid, int srows)
{
    constexpr int WN8 = BN / 32;
    constexpr int AF = 128 * 32;
    constexpr int BF = BN * 32;
    extern __shared__ float sm[];
    float* sA = sm;
    float* sB = sm + STAGES * AF;

    const int z = blockIdx.z;
    int zeff = z;
    const float* Asel = A;
    const float* Bsel = B0; const float* bias = bias0; float* Osel = O0;
    if (EPI == 1) {
        if (z == 1)      { Bsel = B1; bias = bias1; Osel = O1; }
        else if (z == 2) { Bsel = B2; bias = bias2; Osel = O2; }
    }
    if (EPI == 5) {
        zeff = z & 31;
        if (z >= 32) { Asel = B1; Bsel = B2; Osel = O1; }
    }
    const float* Ag = Asel + (size_t)zeff * sAz;
    const float* Bg = Bsel + (size_t)((EPI == 5 || bmod16) ? (zeff & 15) : zeff) * sBz;

    const int tid = threadIdx.x;
    const int m0 = blockIdx.y * 128, n0 = blockIdx.x * BN;
    const uint32_t sA_u = (uint32_t)__cvta_generic_to_shared(sA);
    const uint32_t sB_u = (uint32_t)__cvta_generic_to_shared(sB);

    const int wid = tid >> 5, lane = tid & 31;
    const int wm = wid & 1, wn = wid >> 1;
    const int r = lane >> 2, cq = lane & 3;

    float acc[4][WN8][4];
    #pragma unroll
    for (int mt = 0; mt < 4; mt++)
        #pragma unroll
        for (int nt = 0; nt < WN8; nt++)
            #pragma unroll
            for (int q = 0; q < 4; q++) acc[mt][nt][q] = 0.f;

    auto loadStage = [&](int st, int k0) {
        #pragma unroll
        for (int i = 0; i < 4; i++) {
            int id = tid + i * 256;
            int row = id >> 3, c = id & 7;
            uint32_t dst = sA_u + (uint32_t)((st * AF + row * 32 + ((c ^ (row & 7)) << 2)) << 2);
            cpa16(dst, Ag + (size_t)(m0 + row) * lda + k0 + (c << 2));
        }
        #pragma unroll
        for (int i = 0; i < BN / 32; i++) {
            int id = tid + i * 256;
            int row = id >> 3, c = id & 7;
            uint32_t dst = sB_u + (uint32_t)((st * BF + row * 32 + ((c ^ (row & 7)) << 2)) << 2);
            cpa16(dst, Bg + (size_t)(n0 + row) * ldb + k0 + (c << 2));
        }
    };

    const int nk = K >> 5;
    loadStage(0, 0);  CP_COMMIT();
    loadStage(1, 32); CP_COMMIT();

    for (int it = 0; it < nk; it++) {
        CP_WAIT1();
        __syncthreads();
        int nxt = it + 2;
        if (nxt < nk) loadStage(nxt % STAGES, nxt * 32);
        CP_COMMIT();

        const float* a = sA + (it % STAGES) * AF;
        const float* b = sB + (it % STAGES) * BF;
        #pragma unroll
        for (int ks = 0; ks < 4; ks++) {
            uint32_t af0[4], af1[4], af2[4], af3[4];
            #pragma unroll
            for (int mt = 0; mt < 4; mt++) {
                int R = wm * 64 + mt * 16 + r;
                int r7 = R & 7;
                int lo = ((2 * ks) ^ r7) << 2, hi = ((2 * ks + 1) ^ r7) << 2;
                af0[mt] = __float_as_uint(a[R * 32 + lo + cq]);
                af2[mt] = __float_as_uint(a[R * 32 + hi + cq]);
                af1[mt] = __float_as_uint(a[(R + 8) * 32 + lo + cq]);
                af3[mt] = __float_as_uint(a[(R + 8) * 32 + hi + cq]);
            }
            #pragma unroll
            for (int nt = 0; nt < WN8; nt++) {
                int Nn = wn * WN8 * 8 + nt * 8 + r;
                int n7 = Nn & 7;
                int lo = ((2 * ks) ^ n7) << 2, hi = ((2 * ks + 1) ^ n7) << 2;
                uint32_t b0 = __float_as_uint(b[Nn * 32 + lo + cq]);
                uint32_t b1 = __float_as_uint(b[Nn * 32 + hi + cq]);
                #pragma unroll
                for (int mt = 0; mt < 4; mt++)
                    mma_tf32(acc[mt][nt], af0[mt], af1[mt], af2[mt], af3[mt], b0, b1);
            }
        }
        __syncthreads();
    }

    float* Cz = Osel + (size_t)zeff * sCz;
    #pragma unroll
    for (int mt = 0; mt < 4; mt++) {
        #pragma unroll
        for (int e = 0; e < 2; e++) {
            int gm = m0 + wm * 64 + mt * 16 + r + e * 8;
            #pragma unroll
            for (int nt = 0; nt < WN8; nt++) {
                int gn = n0 + wn * WN8 * 8 + nt * 8 + 2 * cq;
                float v0 = acc[mt][nt][e * 2 + 0];
                float v1 = acc[mt][nt][e * 2 + 1];
                if (EPI == 0 || EPI == 5) {
                    float2 o = {v0, v1};
                    *(float2*)(Cz + (size_t)gm * ldc + gn) = o;
                } else if (EPI == 1) {
                    int h = gn >> 6, d = gn & 63;
                    int b = gm / srows, s = gm % srows;
                    float2 o = {v0 + bias[gn], v1 + bias[gn + 1]};
                    *(float2*)(Osel + ((((size_t)b * HH + h) * srows + s) << 6) + d) = o;
                } else if (EPI == 2) {
                    size_t ad = (size_t)gm * ldc + gn;
                    float2 rr = *(const float2*)(resid + ad);
                    float2 o = {v0 + bias[gn] + rr.x, v1 + bias[gn + 1] + rr.y};
                    *(float2*)(Osel + ad) = o;
                }
            }
        }
    }
}

// -------- weight transpose (with tf32 rounding): Wt[n][k] = tf32(W[k][n]) ----
__global__ void transpose_w(const float* __restrict__ W0, const float* __restrict__ W1,
                            const float* __restrict__ W2, const float* __restrict__ W3)
{
    __shared__ float t[32][33];
    int zz = blockIdx.z;
    const float* W = zz == 0 ? W0 : zz == 1 ? W1 : zz == 2 ? W2 : W3;
    float* Tz = g_Wt + (size_t)zz * DMODEL * DMODEL;
    int x = blockIdx.x * 32 + threadIdx.x;
    int y0 = blockIdx.y * 32;
    #pragma unroll
    for (int i = threadIdx.y; i < 32; i += 8)
        t[i][threadIdx.x] = to_tf32(W[(size_t)(y0 + i) * DMODEL + x]);
    __syncthreads();
    int xo = blockIdx.y * 32 + threadIdx.x;
    int yo0 = blockIdx.x * 32;
    #pragma unroll
    for (int i = threadIdx.y; i < 32; i += 8)
        Tz[(size_t)(yo0 + i) * DMODEL + xo] = t[threadIdx.x][i];
}

// -------- V transpose per head: Vt[bh][d][s] = V[bh][s][d] --------------------
__global__ void transpose_v()
{
    __shared__ float t[32][33];
    int bh = blockIdx.z;
    int s0 = blockIdx.x * 32, d0 = blockIdx.y * 32;
    const float* Vi = g_V + (size_t)bh * SS * DD;
    float* Vo = g_Vt + (size_t)bh * DD * SS;
    #pragma unroll
    for (int i = threadIdx.y; i < 32; i += 8)
        t[i][threadIdx.x] = Vi[(size_t)(s0 + i) * DD + d0 + threadIdx.x];
    __syncthreads();
    #pragma unroll
    for (int i = threadIdx.y; i < 32; i += 8)
        Vo[(size_t)(d0 + i) * SS + s0 + threadIdx.x] = t[threadIdx.x][i];
}

// ============================================================================
// Fused flash attention: scores (QK^T + c2p/p2c gathers, mask) -> online
// softmax -> P@V, per CTA one 128-query tile, loop 16 x 64-key tiles.
// smem: sQ[128][64], sK[64][64], sV(=V^T)[64][64], sP[128][64],
//       redm[4][128], reds[4][128], sidx[1151+1]
// ============================================================================
#define FS_Q 0
#define FS_K 8192
#define FS_V 12288
#define FS_P 16384
#define FS_RM 24576
#define FS_RS 25088
#define FS_IDX 25600
#define FS_TOTAL ((25600 + 1152) * 4)

__global__ __launch_bounds__(256, 2) void flash_kernel(const int* __restrict__ am)
{
    extern __shared__ float fs[];
    float* sQ = fs + FS_Q;
    float* sK = fs + FS_K;
    float* sV = fs + FS_V;
    float* sP = fs + FS_P;
    float* redm = fs + FS_RM;
    float* reds = fs + FS_RS;
    int*   sidx = (int*)(fs + FS_IDX);

    const int bh = blockIdx.y, b = bh >> 4, h = bh & 15;
    const int q0 = blockIdx.x * 128;
    const int tid = threadIdx.x, wid = tid >> 5, lane = tid & 31;
    const int wm = wid & 1, wn = wid >> 1, r = lane >> 2, cq = lane & 3;

    const float* Qg = g_Q + (size_t)bh * SS * DD;
    const float* Kg = g_K + (size_t)bh * SS * DD;
    const float* Vg = g_Vt + (size_t)bh * DD * SS;
    const float* C2Pg = g_C2P + (size_t)bh * SS * PP;
    const float* P2Cg = g_P2C + (size_t)bh * SS * PP;

    const uint32_t smem_u = (uint32_t)__cvta_generic_to_shared(fs);

    for (int i = tid; i < 1151; i += 256) sidx[i] = g_idx[q0 + i];

    auto loadK = [&](int k0) {
        #pragma unroll
        for (int i = 0; i < 4; i++) {
            int id = tid + i * 256;
            int row = id >> 4, c = id & 15;
            uint32_t dst = smem_u + (uint32_t)((FS_K + row * 64 + ((c ^ (row & 7)) << 2)) << 2);
            cpa16(dst, Kg + (size_t)(k0 + row) * DD + (c << 2));
        }
    };
    auto loadV = [&](int k0) {
        #pragma unroll
        for (int i = 0; i < 4; i++) {
            int id = tid + i * 256;
            int row = id >> 4, c = id & 15;   // row = d, c over 64 keys
            uint32_t dst = smem_u + (uint32_t)((FS_V + row * 64 + ((c ^ (row & 7)) << 2)) << 2);
            cpa16(dst, Vg + (size_t)row * SS + k0 + (c << 2));
        }
    };
    // prologue: Q + K0 (group), V0 (group)
    #pragma unroll
    for (int i = 0; i < 8; i++) {
        int id = tid + i * 256;
        int row = id >> 4, c = id & 15;
        uint32_t dst = smem_u + (uint32_t)((FS_Q + row * 64 + ((c ^ (row & 7)) << 2)) << 2);
        cpa16(dst, Qg + (size_t)(q0 + row) * DD + (c << 2));
    }
    loadK(0); CP_COMMIT();
    loadV(0); CP_COMMIT();

    float m_[4][2], l_[4][2], accD[4][2][4];
    #pragma unroll
    for (int mt = 0; mt < 4; mt++)
        #pragma unroll
        for (int e = 0; e < 2; e++) {
            m_[mt][e] = -3.0e38f; l_[mt][e] = 0.f;
            accD[mt][e][0] = accD[mt][e][1] = 0.f;   // accD[mt][nt][..] init below
        }
    #pragma unroll
    for (int mt = 0; mt < 4; mt++)
        #pragma unroll
        for (int nt = 0; nt < 2; nt++)
            #pragma unroll
            for (int q = 0; q < 4; q++) accD[mt][nt][q] = 0.f;

    const int nIt = SS / 64;
    for (int it = 0; it < nIt; it++) {
        const int k0 = it * 64;
        CP_WAIT1();
        __syncthreads();                      // A: K_it ready (Q too at it=0)

        // ---- S = Q K^T tile (128 x 64) ----
        float accS[4][2][4];
        #pragma unroll
        for (int mt = 0; mt < 4; mt++)
            #pragma unroll
            for (int nt = 0; nt < 2; nt++)
                #pragma unroll
                for (int q = 0; q < 4; q++) accS[mt][nt][q] = 0.f;

        #pragma unroll
        for (int ks = 0; ks < 8; ks++) {
            uint32_t af0[4], af1[4], af2[4], af3[4];
            #pragma unroll
            for (int mt = 0; mt < 4; mt++) {
                int R = wm * 64 + mt * 16 + r;
                int r7 = R & 7;
                int lo = ((2 * ks) ^ r7) << 2, hi = ((2 * ks + 1) ^ r7) << 2;
                af0[mt] = __float_as_uint(sQ[R * 64 + lo + cq]);
                af2[mt] = __float_as_uint(sQ[R * 64 + hi + cq]);
                af1[mt] = __float_as_uint(sQ[(R + 8) * 64 + lo + cq]);
                af3[mt] = __float_as_uint(sQ[(R + 8) * 64 + hi + cq]);
            }
            #pragma unroll
            for (int nt = 0; nt < 2; nt++) {
                int n = wn * 16 + nt * 8 + r;
                int n7 = n & 7;
                uint32_t b0 = __float_as_uint(sK[n * 64 + (((2 * ks) ^ n7) << 2) + cq]);
                uint32_t b1 = __float_as_uint(sK[n * 64 + (((2 * ks + 1) ^ n7) << 2) + cq]);
                #pragma unroll
                for (int mt = 0; mt < 4; mt++)
                    mma_tf32(accS[mt][nt], af0[mt], af1[mt], af2[mt], af3[mt], b0, b1);
            }
        }

        // ---- score epilogue: gathers + mask, per-row warp max ----
        #pragma unroll
        for (int mt = 0; mt < 4; mt++) {
            #pragma unroll
            for (int e = 0; e < 2; e++) {
                int R = wm * 64 + mt * 16 + r + e * 8;
                int qg = q0 + R;
                const float* c2pr = C2Pg + (size_t)qg * PP;
                const int* amr = am + ((size_t)(b * SS + qg)) * SS;
                float mx = -3.0e38f;
                #pragma unroll
                for (int nt = 0; nt < 2; nt++) {
                    int kg = k0 + wn * 16 + nt * 8 + 2 * cq;
                    int2 mk = *(const int2*)(amr + kg);
                    #pragma unroll
                    for (int j = 0; j < 2; j++) {
                        int msk = j == 0 ? mk.x : mk.y;
                        float s = -3.0e38f;
                        if (msk) {
                            int id = sidx[R - (kg + j) + 1023];
                            s = (accS[mt][nt][e * 2 + j] + c2pr[id]
                                 + P2Cg[(size_t)(kg + j) * PP + id]) * INV_SCALE;
                        }
                        accS[mt][nt][e * 2 + j] = s;
                        mx = fmaxf(mx, s);
                    }
                }
                mx = fmaxf(mx, __shfl_xor_sync(0xffffffffu, mx, 1));
                mx = fmaxf(mx, __shfl_xor_sync(0xffffffffu, mx, 2));
                if (cq == 0) redm[wn * 128 + R] = mx;
            }
        }
        __syncthreads();                      // B: redm visible; K smem free
        if (it + 1 < nIt) loadK(k0 + 64);
        CP_COMMIT();

        // ---- online softmax update, write P ----
        #pragma unroll
        for (int mt = 0; mt < 4; mt++) {
            #pragma unroll
            for (int e = 0; e < 2; e++) {
                int R = wm * 64 + mt * 16 + r + e * 8;
                float tmax = fmaxf(fmaxf(redm[R], redm[128 + R]),
                                   fmaxf(redm[256 + R], redm[384 + R]));
                float mnew = fmaxf(m_[mt][e], tmax);
                float alpha = __expf(m_[mt][e] - mnew);
                m_[mt][e] = mnew;
                float psum = 0.f;
                #pragma unroll
                for (int nt = 0; nt < 2; nt++) {
                    float s0 = accS[mt][nt][e * 2 + 0];
                    float s1 = accS[mt][nt][e * 2 + 1];
                    float p0 = (s0 < -1.0e37f) ? 0.f : __expf(s0 - mnew);
                    float p1 = (s1 < -1.0e37f) ? 0.f : __expf(s1 - mnew);
                    psum += p0 + p1;
                    int col = wn * 16 + nt * 8 + 2 * cq;
                    int chunk = (col >> 2) ^ (R & 7);
                    float2 pr = {p0, p1};
                    *(float2*)&sP[R * 64 + (chunk << 2) + (col & 3)] = pr;
                    accD[mt][nt][e * 2 + 0] *= alpha;
                    accD[mt][nt][e * 2 + 1] *= alpha;
                }
                psum += __shfl_xor_sync(0xffffffffu, psum, 1);
                psum += __shfl_xor_sync(0xffffffffu, psum, 2);
                if (cq == 0) reds[wn * 128 + R] = psum;
                l_[mt][e] *= alpha;
            }
        }
        if (it + 1 < nIt) { CP_WAIT1(); } else { CP_WAIT0(); }   // V_it done
        __syncthreads();                      // C: reds + P visible, V ready
        #pragma unroll
        for (int mt = 0; mt < 4; mt++)
            #pragma unroll
            for (int e = 0; e < 2; e++) {
                int R = wm * 64 + mt * 16 + r + e * 8;
                l_[mt][e] += reds[R] + reds[128 + R] + reds[256 + R] + reds[384 + R];
            }

        // ---- PV: accD += P @ V  (A = sP 128x64, B = sV = V^T 64x64) ----
        #pragma unroll
        for (int ks = 0; ks < 8; ks++) {
            uint32_t af0[4], af1[4], af2[4], af3[4];
            #pragma unroll
            for (int mt = 0; mt < 4; mt++) {
                int R = wm * 64 + mt * 16 + r;
                int r7 = R & 7;
                int lo = ((2 * ks) ^ r7) << 2, hi = ((2 * ks + 1) ^ r7) << 2;
                af0[mt] = __float_as_uint(sP[R * 64 + lo + cq]);
                af2[mt] = __float_as_uint(sP[R * 64 + hi + cq]);
                af1[mt] = __float_as_uint(sP[(R + 8) * 64 + lo + cq]);
                af3[mt] = __float_as_uint(sP[(R + 8) * 64 + hi + cq]);
            }
            #pragma unroll
            for (int nt = 0; nt < 2; nt++) {
                int n = wn * 16 + nt * 8 + r;   // d index
                int n7 = n & 7;
                uint32_t b0 = __float_as_uint(sV[n * 64 + (((2 * ks) ^ n7) << 2) + cq]);
                uint32_t b1 = __float_as_uint(sV[n * 64 + (((2 * ks + 1) ^ n7) << 2) + cq]);
                #pragma unroll
                for (int mt = 0; mt < 4; mt++)
                    mma_tf32(accD[mt][nt], af0[mt], af1[mt], af2[mt], af3[mt], b0, b1);
            }
        }
        __syncthreads();                      // D: P, V free
        if (it + 1 < nIt) loadV(k0 + 64);
        CP_COMMIT();
    }

    // ---- final: normalize by 1/l, write ctx ----
    #pragma unroll
    for (int mt = 0; mt < 4; mt++) {
        #pragma unroll
        for (int e = 0; e < 2; e++) {
            int R = wm * 64 + mt * 16 + r + e * 8;
            int qg = q0 + R;
            float inv = l_[mt][e] > 0.f ? 1.f / l_[mt][e] : 0.f;
            #pragma unroll
            for (int nt = 0; nt < 2; nt++) {
                int d = wn * 16 + nt * 8 + 2 * cq;
                float2 o = {accD[mt][nt][e * 2 + 0] * inv, accD[mt][nt][e * 2 + 1] * inv};
                *(float2*)(g_ctx + (size_t)(b * SS + qg) * DMODEL + h * DD + d) = o;
            }
        }
    }
}

// ---------------- layernorm of g_H, write to output --------------------------
__global__ __launch_bounds__(256) void ln_kernel(
    const float* __restrict__ lw, const float* __restrict__ lb,
    float* __restrict__ out)
{
    __shared__ float red[256];
    __shared__ float red2[256];
    int r = blockIdx.x, t = threadIdx.x;
    const float* x = g_H + (size_t)r * DMODEL;
    float s = 0.f, s2 = 0.f;
    #pragma unroll
    for (int i = 0; i < 4; i++) {
        float v = x[t + i * 256];
        s += v; s2 += v * v;
    }
    red[t] = s; red2[t] = s2; __syncthreads();
    for (int st = 128; st; st >>= 1) {
        if (t < st) { red[t] += red[t + st]; red2[t] += red2[t + st]; }
        __syncthreads();
    }
    float mu = red[0] * (1.f / DMODEL);
    float var = red2[0] * (1.f / DMODEL) - mu * mu;
    float inv = rsqrtf(var + 1e-7f);
    #pragma unroll
    for (int i = 0; i < 4; i++) {
        int c = t + i * 256;
        out[(size_t)r * DMODEL + c] = (x[c] - mu) * inv * lw[c] + lb[c];
    }
}

// ---------------- launch ------------------------------------------------------
extern "C" void kernel_launch(void* const* d_in, const int* in_sizes, int n_in,
                              void* d_out, int out_size)
{
    const float* hs  = (const float*)d_in[0];
    const float* rel = (const float*)d_in[1];
    const float* Wq  = (const float*)d_in[2];  const float* bq = (const float*)d_in[3];
    const float* Wk  = (const float*)d_in[4];  const float* bk = (const float*)d_in[5];
    const float* Wv  = (const float*)d_in[6];  const float* bv = (const float*)d_in[7];
    const float* Wo  = (const float*)d_in[8];  const float* bo = (const float*)d_in[9];
    const float* lw  = (const float*)d_in[10]; const float* lb = (const float*)d_in[11];
    const int*   am  = (const int*)d_in[12];
    float* out = (float*)d_out;

    float *Q_, *K_, *V_, *PK_, *PQ_, *WT_, *C2P_, *P2C_, *CTX_, *Hb_;
    cudaGetSymbolAddress((void**)&Q_,   g_Q);
    cudaGetSymbolAddress((void**)&K_,   g_K);
    cudaGetSymbolAddress((void**)&V_,   g_V);
    cudaGetSymbolAddress((void**)&PK_,  g_posK);
    cudaGetSymbolAddress((void**)&PQ_,  g_posQ);
    cudaGetSymbolAddress((void**)&WT_,  g_Wt);
    cudaGetSymbolAddress((void**)&C2P_, g_C2P);
    cudaGetSymbolAddress((void**)&P2C_, g_P2C);
    cudaGetSymbolAddress((void**)&CTX_, g_ctx);
    cudaGetSymbolAddress((void**)&Hb_,  g_H);

    const float* WtQ = WT_;
    const float* WtK = WT_ + (size_t)1 * DMODEL * DMODEL;
    const float* WtV = WT_ + (size_t)2 * DMODEL * DMODEL;
    const float* WtO = WT_ + (size_t)3 * DMODEL * DMODEL;

    const int SM128 = STAGES * (128 * 32 + 128 * 32) * 4;   // 98304
    cudaFuncSetAttribute(mm_nt<128,1>, cudaFuncAttributeMaxDynamicSharedMemorySize, SM128);
    cudaFuncSetAttribute(mm_nt<128,2>, cudaFuncAttributeMaxDynamicSharedMemorySize, SM128);
    cudaFuncSetAttribute(mm_nt<128,5>, cudaFuncAttributeMaxDynamicSharedMemorySize, SM128);
    cudaFuncSetAttribute(flash_kernel, cudaFuncAttributeMaxDynamicSharedMemorySize, FS_TOTAL);

    build_idx_kernel<<<8, 256>>>();
    transpose_w<<<dim3(32, 32, 4), dim3(32, 8)>>>(Wq, Wk, Wv, Wo);

    // QKV projections (merged, head-major out)
    mm_nt<128,1><<<dim3(8,16,3),256,SM128>>>(hs,1024,0, WtQ,WtK,WtV, 1024,0,0,
                                             Q_,K_,V_, 0,0, 1024, bq,bk,bv, nullptr, SS);
    transpose_v<<<dim3(32, 2, 32), dim3(32, 8)>>>();

    // position projections (merged)
    mm_nt<128,1><<<dim3(8,4,2),256,SM128>>>(rel,1024,0, WtK,WtQ,nullptr, 1024,0,0,
                                            PK_,PQ_,nullptr, 0,0, 1024, bk,bq,nullptr, nullptr, PP);

    // disentangled bias tables, merged: z<32 -> C2P = Q @ posK^T ; z>=32 -> P2C = K @ posQ^T
    mm_nt<128,5><<<dim3(4,8,64),256,SM128>>>(Q_,64,(long long)SS*DD, PK_, K_, PQ_,
                                             64,(long long)PP*DD,1,
                                             C2P_,P2C_,nullptr, PP,(long long)SS*PP, 64,
                                             nullptr,nullptr,nullptr, nullptr, 0);

    // fused scores + softmax + PV
    flash_kernel<<<dim3(8, 32), 256, FS_TOTAL>>>(am);

    // output projection + residual, then layernorm
    mm_nt<128,2><<<dim3(8,16,1),256,SM128>>>(CTX_,1024,0, WtO,nullptr,nullptr, 1024,0,0,
                                             Hb_,nullptr,nullptr, 1024,0, 1024,
                                             bo,nullptr,nullptr, hs, 0);
    ln_kernel<<<BB*SS, 256>>>(lw, lb, out);
}

// round 6
// speedup vs baseline: 1.3511x; 1.3511x over previous
#include <cuda_runtime.h>
#include <math.h>
#include <stdint.h>

#define BB 2
#define SS 1024
#define DMODEL 1024
#define HH 16
#define DD 64
#define PP 512               // 2*SPAN
#define BH (BB*HH)
#define INV_SCALE 0.07216878364870323f   // 1/sqrt(192)
#define STAGES 3

// ---------------- scratch (static device memory; no allocs allowed) ----------
__device__ float g_Q[BH*SS*DD];      // [bh][s][64]
__device__ float g_K[BH*SS*DD];
__device__ float g_V[BH*SS*DD];
__device__ float g_Vt[BH*DD*SS];     // [bh][64][s]
__device__ float g_posK[HH*PP*DD];   // [h][p][64]
__device__ float g_posQ[HH*PP*DD];
__device__ float g_Wt[4u*DMODEL*DMODEL]; // Wq^T, Wk^T, Wv^T, Wo^T
__device__ float g_C2P[(size_t)BH*SS*PP];   // [bh][q][p]
__device__ float g_P2Ct[(size_t)BH*PP*SS];  // [bh][p][k]  (transposed!)
__device__ float g_S[(size_t)BH*SS*SS];
__device__ float g_ctx[BB*SS*DMODEL];
__device__ float g_H[BB*SS*DMODEL];
__device__ int   g_idx[2047];

// ---------------- idx table: clip(bucket(delta)+256, 0, 511) -----------------
__global__ void build_idx_kernel() {
    int t = blockIdx.x * blockDim.x + threadIdx.x;
    if (t >= 2047) return;
    int rel = t - 1023;
    int bucket;
    if (rel > -128 && rel < 128) {
        bucket = rel;
    } else {
        double abs_pos = fabs((double)rel);
        if (abs_pos <= 128.0) {
            bucket = rel;
        } else {
            int sgn = (rel > 0) - (rel < 0);
            double lp = ceil(log(abs_pos / 128.0) / log(511.0 / 128.0) * 127.0) + 128.0;
            bucket = (int)lp * sgn;
        }
    }
    int i1 = bucket + 256;
    i1 = i1 < 0 ? 0 : (i1 > 511 ? 511 : i1);
    g_idx[t] = i1;
}

__device__ __forceinline__ float to_tf32(float x) {
    float y;
    asm("cvt.rna.tf32.f32 %0, %1;" : "=f"(y) : "f"(x));
    return y;
}

__device__ __forceinline__ void mma_tf32(float (&d)[4],
                                         uint32_t a0, uint32_t a1, uint32_t a2, uint32_t a3,
                                         uint32_t b0, uint32_t b1) {
    asm volatile(
        "mma.sync.aligned.m16n8k8.row.col.f32.tf32.tf32.f32 "
        "{%0,%1,%2,%3}, {%4,%5,%6,%7}, {%8,%9}, {%0,%1,%2,%3};\n"
        : "+f"(d[0]), "+f"(d[1]), "+f"(d[2]), "+f"(d[3])
        : "r"(a0), "r"(a1), "r"(a2), "r"(a3), "r"(b0), "r"(b1));
}

__device__ __forceinline__ void cpa16(uint32_t s, const float* g) {
    asm volatile("cp.async.cg.shared.global [%0], [%1], 16;\n" :: "r"(s), "l"(g));
}
#define CP_COMMIT() asm volatile("cp.async.commit_group;\n" ::: "memory")
#define CP_WAIT1()  asm volatile("cp.async.wait_group 1;\n" ::: "memory")
#define CP_WAIT0()  asm volatile("cp.async.wait_group 0;\n" ::: "memory")

// ============================================================================
// NT tf32 GEMM, 3-stage cp.async pipeline, XOR-swizzled smem.
//   C[z] = A[z] (MxK row-major) @ B[z] (NxK row-major)^T + epilogue
// mods: bit0 -> B index z&15 ; bit1 -> A index z&15
// EPI 0: plain store   EPI 1: head-major scatter + bias (z selects B/bias/O)
// EPI 2: +bias+resid   EPI 3: scores = (QK + c2p gather)*scale, mask -> -3e38
//                              (resid param doubles as mask pointer)
// ============================================================================
template<int BN, int EPI>
__global__ __launch_bounds__(256) void mm_nt(
    const float* __restrict__ A, int lda, long long sAz,
    const float* __restrict__ B0, const float* __restrict__ B1, const float* __restrict__ B2,
    int ldb, long long sBz, int mods,
    float* __restrict__ O0, float* __restrict__ O1, float* __restrict__ O2,
    int ldc, long long sCz, int K,
    const float* __restrict__ bias0, const float* __restrict__ bias1, const float* __restrict__ bias2,
    const float* __restrict__ resid, int srows)
{
    constexpr int WN8 = BN / 32;
    constexpr int AF = 128 * 32;
    constexpr int BF = BN * 32;
    extern __shared__ float sm[];
    float* sA = sm;
    float* sB = sm + STAGES * AF;

    const int z = blockIdx.z;
    const float* Bsel = B0; const float* bias = bias0; float* Osel = O0;
    if (EPI == 1) {
        if (z == 1)      { Bsel = B1; bias = bias1; Osel = O1; }
        else if (z == 2) { Bsel = B2; bias = bias2; Osel = O2; }
    }
    const float* Ag = A + (size_t)((mods & 2) ? (z & 15) : z) * sAz;
    const float* Bg = Bsel + (size_t)((mods & 1) ? (z & 15) : z) * sBz;

    const int tid = threadIdx.x;
    const int m0 = blockIdx.y * 128, n0 = blockIdx.x * BN;
    const uint32_t sA_u = (uint32_t)__cvta_generic_to_shared(sA);
    const uint32_t sB_u = (uint32_t)__cvta_generic_to_shared(sB);

    const int wid = tid >> 5, lane = tid & 31;
    const int wm = wid & 1, wn = wid >> 1;
    const int r = lane >> 2, cq = lane & 3;

    float acc[4][WN8][4];
    #pragma unroll
    for (int mt = 0; mt < 4; mt++)
        #pragma unroll
        for (int nt = 0; nt < WN8; nt++)
            #pragma unroll
            for (int q = 0; q < 4; q++) acc[mt][nt][q] = 0.f;

    auto loadStage = [&](int st, int k0) {
        #pragma unroll
        for (int i = 0; i < 4; i++) {
            int id = tid + i * 256;
            int row = id >> 3, c = id & 7;
            uint32_t dst = sA_u + (uint32_t)((st * AF + row * 32 + ((c ^ (row & 7)) << 2)) << 2);
            cpa16(dst, Ag + (size_t)(m0 + row) * lda + k0 + (c << 2));
        }
        #pragma unroll
        for (int i = 0; i < BN / 32; i++) {
            int id = tid + i * 256;
            int row = id >> 3, c = id & 7;
            uint32_t dst = sB_u + (uint32_t)((st * BF + row * 32 + ((c ^ (row & 7)) << 2)) << 2);
            cpa16(dst, Bg + (size_t)(n0 + row) * ldb + k0 + (c << 2));
        }
    };

    const int nk = K >> 5;
    loadStage(0, 0);  CP_COMMIT();
    loadStage(1, 32); CP_COMMIT();

    for (int it = 0; it < nk; it++) {
        CP_WAIT1();
        __syncthreads();
        int nxt = it + 2;
        if (nxt < nk) loadStage(nxt % STAGES, nxt * 32);
        CP_COMMIT();

        const float* a = sA + (it % STAGES) * AF;
        const float* b = sB + (it % STAGES) * BF;
        #pragma unroll
        for (int ks = 0; ks < 4; ks++) {
            uint32_t af0[4], af1[4], af2[4], af3[4];
            #pragma unroll
            for (int mt = 0; mt < 4; mt++) {
                int R = wm * 64 + mt * 16 + r;
                int r7 = R & 7;
                int lo = ((2 * ks) ^ r7) << 2, hi = ((2 * ks + 1) ^ r7) << 2;
                af0[mt] = __float_as_uint(a[R * 32 + lo + cq]);
                af2[mt] = __float_as_uint(a[R * 32 + hi + cq]);
                af1[mt] = __float_as_uint(a[(R + 8) * 32 + lo + cq]);
                af3[mt] = __float_as_uint(a[(R + 8) * 32 + hi + cq]);
            }
            #pragma unroll
            for (int nt = 0; nt < WN8; nt++) {
                int Nn = wn * WN8 * 8 + nt * 8 + r;
                int n7 = Nn & 7;
                int lo = ((2 * ks) ^ n7) << 2, hi = ((2 * ks + 1) ^ n7) << 2;
                uint32_t b0 = __float_as_uint(b[Nn * 32 + lo + cq]);
                uint32_t b1 = __float_as_uint(b[Nn * 32 + hi + cq]);
                #pragma unroll
                for (int mt = 0; mt < 4; mt++)
                    mma_tf32(acc[mt][nt], af0[mt], af1[mt], af2[mt], af3[mt], b0, b1);
            }
        }
        __syncthreads();
    }

    float* Cz = Osel + (size_t)z * sCz;
    #pragma unroll
    for (int mt = 0; mt < 4; mt++) {
        #pragma unroll
        for (int e = 0; e < 2; e++) {
            int gm = m0 + wm * 64 + mt * 16 + r + e * 8;
            #pragma unroll
            for (int nt = 0; nt < WN8; nt++) {
                int gn = n0 + wn * WN8 * 8 + nt * 8 + 2 * cq;
                float v0 = acc[mt][nt][e * 2 + 0];
                float v1 = acc[mt][nt][e * 2 + 1];
                if (EPI == 0) {
                    float2 o = {v0, v1};
                    *(float2*)(Cz + (size_t)gm * ldc + gn) = o;
                } else if (EPI == 1) {
                    int h = gn >> 6, d = gn & 63;
                    int b = gm / srows, s = gm % srows;
                    float2 o = {v0 + bias[gn], v1 + bias[gn + 1]};
                    *(float2*)(Osel + ((((size_t)b * HH + h) * srows + s) << 6) + d) = o;
                } else if (EPI == 2) {
                    size_t ad = (size_t)gm * ldc + gn;
                    float2 rr = *(const float2*)(resid + ad);
                    float2 o = {v0 + bias[gn] + rr.x, v1 + bias[gn + 1] + rr.y};
                    *(float2*)(Osel + ad) = o;
                } else if (EPI == 3) {
                    int id0 = g_idx[gm - gn + 1023];
                    int id1 = g_idx[gm - gn + 1022];
                    size_t cb = ((size_t)z * SS + gm) * PP;
                    const int* amr = (const int*)resid + ((size_t)((z >> 4) * SS + gm)) * SS;
                    int2 mk = *(const int2*)(amr + gn);
                    float o0 = mk.x ? (v0 + g_C2P[cb + id0]) * INV_SCALE : -3.0e38f;
                    float o1 = mk.y ? (v1 + g_C2P[cb + id1]) * INV_SCALE : -3.0e38f;
                    float2 o = {o0, o1};
                    *(float2*)(Cz + (size_t)gm * ldc + gn) = o;
                }
            }
        }
    }
}

// -------- weight transpose (with tf32 rounding): Wt[n][k] = tf32(W[k][n]) ----
__global__ void transpose_w(const float* __restrict__ W0, const float* __restrict__ W1,
                            const float* __restrict__ W2, const float* __restrict__ W3)
{
    __shared__ float t[32][33];
    int zz = blockIdx.z;
    const float* W = zz == 0 ? W0 : zz == 1 ? W1 : zz == 2 ? W2 : W3;
    float* Tz = g_Wt + (size_t)zz * DMODEL * DMODEL;
    int x = blockIdx.x * 32 + threadIdx.x;
    int y0 = blockIdx.y * 32;
    #pragma unroll
    for (int i = threadIdx.y; i < 32; i += 8)
        t[i][threadIdx.x] = to_tf32(W[(size_t)(y0 + i) * DMODEL + x]);
    __syncthreads();
    int xo = blockIdx.y * 32 + threadIdx.x;
    int yo0 = blockIdx.x * 32;
    #pragma unroll
    for (int i = threadIdx.y; i < 32; i += 8)
        Tz[(size_t)(yo0 + i) * DMODEL + xo] = t[threadIdx.x][i];
}

// -------- V transpose per head: Vt[bh][d][s] = V[bh][s][d] --------------------
__global__ void transpose_v()
{
    __shared__ float t[32][33];
    int bh = blockIdx.z;
    int s0 = blockIdx.x * 32, d0 = blockIdx.y * 32;
    const float* Vi = g_V + (size_t)bh * SS * DD;
    float* Vo = g_Vt + (size_t)bh * DD * SS;
    #pragma unroll
    for (int i = threadIdx.y; i < 32; i += 8)
        t[i][threadIdx.x] = Vi[(size_t)(s0 + i) * DD + d0 + threadIdx.x];
    __syncthreads();
    #pragma unroll
    for (int i = threadIdx.y; i < 32; i += 8)
        Vo[(size_t)(d0 + i) * SS + s0 + threadIdx.x] = t[threadIdx.x][i];
}

// ============================================================================
// Fused p2c-bias + online softmax + PV.
// CTA: 128 q-rows x one bh; loop 16 x 64-key tiles (double-buffered cp.async).
// Per tile:  S += p2c (diagonal-coalesced from P2Ct) -> softmax -> P@V.
// smem: sS[2][128][64], sV[2][64][64], redm[4][128], reds[4][128], sidx[1152]
// ============================================================================
#define SP_V   16384
#define SP_RM  24576
#define SP_RS  25088
#define SP_IDX 25600
#define SP_TOTAL ((25600 + 1152) * 4)

__global__ __launch_bounds__(256, 2) void softpv_kernel()
{
    extern __shared__ float fs[];
    float* redm = fs + SP_RM;
    float* reds = fs + SP_RS;
    int*   sidx = (int*)(fs + SP_IDX);

    const int bh = blockIdx.y, b = bh >> 4, h = bh & 15;
    const int q0 = blockIdx.x * 128;
    const int tid = threadIdx.x, wid = tid >> 5, lane = tid & 31;
    const int wm = wid & 1, wn = wid >> 1, r = lane >> 2, cq = lane & 3;

    const float* Sg  = g_S + (size_t)bh * SS * SS + (size_t)q0 * SS;
    const float* Vg  = g_Vt + (size_t)bh * DD * SS;
    const float* P2g = g_P2Ct + (size_t)bh * PP * SS;

    const uint32_t smem_u = (uint32_t)__cvta_generic_to_shared(fs);

    for (int i = tid; i < 1151; i += 256) sidx[i] = g_idx[q0 + i];

    auto loadS = [&](int st, int k0) {
        #pragma unroll
        for (int i = 0; i < 8; i++) {
            int id = tid + i * 256;
            int row = id >> 4, c = id & 15;
            uint32_t dst = smem_u + (uint32_t)((st * 8192 + row * 64 + ((c ^ (row & 7)) << 2)) << 2);
            cpa16(dst, Sg + (size_t)row * SS + k0 + (c << 2));
        }
    };
    auto loadV = [&](int st, int k0) {
        #pragma unroll
        for (int i = 0; i < 4; i++) {
            int id = tid + i * 256;
            int row = id >> 4, c = id & 15;
            uint32_t dst = smem_u + (uint32_t)((SP_V + st * 4096 + row * 64 + ((c ^ (row & 7)) << 2)) << 2);
            cpa16(dst, Vg + (size_t)row * SS + k0 + (c << 2));
        }
    };

    loadS(0, 0);  loadV(0, 0);  CP_COMMIT();
    loadS(1, 64); loadV(1, 64); CP_COMMIT();

    float m_[4][2], l_[4][2], accD[4][2][4];
    #pragma unroll
    for (int mt = 0; mt < 4; mt++)
        #pragma unroll
        for (int e = 0; e < 2; e++) { m_[mt][e] = -3.0e38f; l_[mt][e] = 0.f; }
    #pragma unroll
    for (int mt = 0; mt < 4; mt++)
        #pragma unroll
        for (int nt = 0; nt < 2; nt++)
            #pragma unroll
            for (int q = 0; q < 4; q++) accD[mt][nt][q] = 0.f;

    const int nIt = SS / 64;
    for (int it = 0; it < nIt; it++) {
        const int k0 = it * 64;
        const int st = it & 1;
        float* tS = fs + st * 8192;
        const float* tV = fs + SP_V + st * 4096;

        CP_WAIT1();
        __syncthreads();                      // S_it, V_it ready

        // ---- p2c diagonal add: d = q-k in [q0-k0-63, q0-k0+127], 191 diags ----
        // sidx offset: t = 960 - k0 + j for diag j.
        #pragma unroll 4
        for (int jj = 0; jj < 24; jj++) {
            int j = wid + jj * 8;
            bool act = j < 191;
            int id = act ? sidx[960 - k0 + j] : 0;
            int d = q0 - k0 - 63 + j;
            const float* prow = P2g + (size_t)id * SS + k0;
            float v0 = act ? prow[lane] : 0.f;
            float v1 = act ? prow[lane + 32] : 0.f;
            #pragma unroll
            for (int half = 0; half < 2; half++) {
                int kl = lane + half * 32;
                int ql = kl + d - q0 + k0 + q0 - q0;   // q_local = kl + (d - (q0-k0))
                ql = kl + (d - (q0 - k0));
                float add = (half == 0 ? v0 : v1) * INV_SCALE;
                if (act && ql >= 0 && ql < 128) {
                    int addr = ql * 64 + (((kl >> 2) ^ (ql & 7)) << 2) + (kl & 3);
                    tS[addr] += add;
                }
            }
        }
        __syncthreads();                      // bias applied

        // ---- softmax: read fragments, row max, exp, write P in place ----
        float sv[4][2][4];
        #pragma unroll
        for (int mt = 0; mt < 4; mt++) {
            #pragma unroll
            for (int e = 0; e < 2; e++) {
                int R = wm * 64 + mt * 16 + r + e * 8;
                float mx = -3.0e38f;
                #pragma unroll
                for (int nt = 0; nt < 2; nt++) {
                    int col = wn * 16 + nt * 8 + 2 * cq;
                    float2 s2 = *(const float2*)&tS[R * 64 + (((col >> 2) ^ (R & 7)) << 2) + (col & 3)];
                    sv[mt][nt][e * 2 + 0] = s2.x;
                    sv[mt][nt][e * 2 + 1] = s2.y;
                    mx = fmaxf(mx, fmaxf(s2.x, s2.y));
                }
                mx = fmaxf(mx, __shfl_xor_sync(0xffffffffu, mx, 1));
                mx = fmaxf(mx, __shfl_xor_sync(0xffffffffu, mx, 2));
                if (cq == 0) redm[wn * 128 + R] = mx;
            }
        }
        __syncthreads();                      // redm visible

        #pragma unroll
        for (int mt = 0; mt < 4; mt++) {
            #pragma unroll
            for (int e = 0; e < 2; e++) {
                int R = wm * 64 + mt * 16 + r + e * 8;
                float tmax = fmaxf(fmaxf(redm[R], redm[128 + R]),
                                   fmaxf(redm[256 + R], redm[384 + R]));
                float mnew = fmaxf(m_[mt][e], tmax);
                float alpha = __expf(m_[mt][e] - mnew);
                m_[mt][e] = mnew;
                float psum = 0.f;
                #pragma unroll
                for (int nt = 0; nt < 2; nt++) {
                    float s0 = sv[mt][nt][e * 2 + 0];
                    float s1 = sv[mt][nt][e * 2 + 1];
                    float p0 = (s0 < -1.0e37f) ? 0.f : __expf(s0 - mnew);
                    float p1 = (s1 < -1.0e37f) ? 0.f : __expf(s1 - mnew);
                    psum += p0 + p1;
                    int col = wn * 16 + nt * 8 + 2 * cq;
                    float2 pr = {p0, p1};
                    *(float2*)&tS[R * 64 + (((col >> 2) ^ (R & 7)) << 2) + (col & 3)] = pr;
                    accD[mt][nt][e * 2 + 0] *= alpha;
                    accD[mt][nt][e * 2 + 1] *= alpha;
                }
                psum += __shfl_xor_sync(0xffffffffu, psum, 1);
                psum += __shfl_xor_sync(0xffffffffu, psum, 2);
                if (cq == 0) reds[wn * 128 + R] = psum;
                l_[mt][e] *= alpha;
            }
        }
        __syncthreads();                      // P + reds visible

        #pragma unroll
        for (int mt = 0; mt < 4; mt++)
            #pragma unroll
            for (int e = 0; e < 2; e++) {
                int R = wm * 64 + mt * 16 + r + e * 8;
                l_[mt][e] += reds[R] + reds[128 + R] + reds[256 + R] + reds[384 + R];
            }

        // ---- PV: accD += P @ V  (A = tS (P) 128x64, B = tV = V^T 64x64) ----
        #pragma unroll
        for (int ks = 0; ks < 8; ks++) {
            uint32_t af0[4], af1[4], af2[4], af3[4];
            #pragma unroll
            for (int mt = 0; mt < 4; mt++) {
                int R = wm * 64 + mt * 16 + r;
                int r7 = R & 7;
                int lo = ((2 * ks) ^ r7) << 2, hi = ((2 * ks + 1) ^ r7) << 2;
                af0[mt] = __float_as_uint(tS[R * 64 + lo + cq]);
                af2[mt] = __float_as_uint(tS[R * 64 + hi + cq]);
                af1[mt] = __float_as_uint(tS[(R + 8) * 64 + lo + cq]);
                af3[mt] = __float_as_uint(tS[(R + 8) * 64 + hi + cq]);
            }
            #pragma unroll
            for (int nt = 0; nt < 2; nt++) {
                int n = wn * 16 + nt * 8 + r;   // d index
                int n7 = n & 7;
                uint32_t b0 = __float_as_uint(tV[n * 64 + (((2 * ks) ^ n7) << 2) + cq]);
                uint32_t b1 = __float_as_uint(tV[n * 64 + (((2 * ks + 1) ^ n7) << 2) + cq]);
                #pragma unroll
                for (int mt = 0; mt < 4; mt++)
                    mma_tf32(accD[mt][nt], af0[mt], af1[mt], af2[mt], af3[mt], b0, b1);
            }
        }
        __syncthreads();                      // tS/tV free for refill

        if (it + 2 < nIt) { loadS(st, k0 + 128); loadV(st, k0 + 128); }
        CP_COMMIT();
    }

    // ---- final: normalize by 1/l, write ctx ----
    #pragma unroll
    for (int mt = 0; mt < 4; mt++) {
        #pragma unroll
        for (int e = 0; e < 2; e++) {
            int R = wm * 64 + mt * 16 + r + e * 8;
            int qg = q0 + R;
            float inv = l_[mt][e] > 0.f ? 1.f / l_[mt][e] : 0.f;
            #pragma unroll
            for (int nt = 0; nt < 2; nt++) {
                int d = wn * 16 + nt * 8 + 2 * cq;
                float2 o = {accD[mt][nt][e * 2 + 0] * inv, accD[mt][nt][e * 2 + 1] * inv};
                *(float2*)(g_ctx + (size_t)(b * SS + qg) * DMODEL + h * DD + d) = o;
            }
        }
    }
}

// ---------------- layernorm of g_H, write to output --------------------------
__global__ __launch_bounds__(256) void ln_kernel(
    const float* __restrict__ lw, const float* __restrict__ lb,
    float* __restrict__ out)
{
    __shared__ float red[256];
    __shared__ float red2[256];
    int r = blockIdx.x, t = threadIdx.x;
    const float* x = g_H + (size_t)r * DMODEL;
    float s = 0.f, s2 = 0.f;
    #pragma unroll
    for (int i = 0; i < 4; i++) {
        float v = x[t + i * 256];
        s += v; s2 += v * v;
    }
    red[t] = s; red2[t] = s2; __syncthreads();
    for (int st = 128; st; st >>= 1) {
        if (t < st) { red[t] += red[t + st]; red2[t] += red2[t + st]; }
        __syncthreads();
    }
    float mu = red[0] * (1.f / DMODEL);
    float var = red2[0] * (1.f / DMODEL) - mu * mu;
    float inv = rsqrtf(var + 1e-7f);
    #pragma unroll
    for (int i = 0; i < 4; i++) {
        int c = t + i * 256;
        out[(size_t)r * DMODEL + c] = (x[c] - mu) * inv * lw[c] + lb[c];
    }
}

// ---------------- launch ------------------------------------------------------
extern "C" void kernel_launch(void* const* d_in, const int* in_sizes, int n_in,
                              void* d_out, int out_size)
{
    const float* hs  = (const float*)d_in[0];
    const float* rel = (const float*)d_in[1];
    const float* Wq  = (const float*)d_in[2];  const float* bq = (const float*)d_in[3];
    const float* Wk  = (const float*)d_in[4];  const float* bk = (const float*)d_in[5];
    const float* Wv  = (const float*)d_in[6];  const float* bv = (const float*)d_in[7];
    const float* Wo  = (const float*)d_in[8];  const float* bo = (const float*)d_in[9];
    const float* lw  = (const float*)d_in[10]; const float* lb = (const float*)d_in[11];
    const int*   am  = (const int*)d_in[12];
    float* out = (float*)d_out;

    float *Q_, *K_, *V_, *PK_, *PQ_, *WT_, *C2P_, *P2CT_, *S_, *CTX_, *Hb_;
    cudaGetSymbolAddress((void**)&Q_,    g_Q);
    cudaGetSymbolAddress((void**)&K_,    g_K);
    cudaGetSymbolAddress((void**)&V_,    g_V);
    cudaGetSymbolAddress((void**)&PK_,   g_posK);
    cudaGetSymbolAddress((void**)&PQ_,   g_posQ);
    cudaGetSymbolAddress((void**)&WT_,   g_Wt);
    cudaGetSymbolAddress((void**)&C2P_,  g_C2P);
    cudaGetSymbolAddress((void**)&P2CT_, g_P2Ct);
    cudaGetSymbolAddress((void**)&S_,    g_S);
    cudaGetSymbolAddress((void**)&CTX_,  g_ctx);
    cudaGetSymbolAddress((void**)&Hb_,   g_H);

    const float* WtQ = WT_;
    const float* WtK = WT_ + (size_t)1 * DMODEL * DMODEL;
    const float* WtV = WT_ + (size_t)2 * DMODEL * DMODEL;
    const float* WtO = WT_ + (size_t)3 * DMODEL * DMODEL;

    const int SM128 = STAGES * (128 * 32 + 128 * 32) * 4;   // 98304
    cudaFuncSetAttribute(mm_nt<128,0>, cudaFuncAttributeMaxDynamicSharedMemorySize, SM128);
    cudaFuncSetAttribute(mm_nt<128,1>, cudaFuncAttributeMaxDynamicSharedMemorySize, SM128);
    cudaFuncSetAttribute(mm_nt<128,2>, cudaFuncAttributeMaxDynamicSharedMemorySize, SM128);
    cudaFuncSetAttribute(mm_nt<128,3>, cudaFuncAttributeMaxDynamicSharedMemorySize, SM128);
    cudaFuncSetAttribute(softpv_kernel, cudaFuncAttributeMaxDynamicSharedMemorySize, SP_TOTAL);

    build_idx_kernel<<<8, 256>>>();
    transpose_w<<<dim3(32, 32, 4), dim3(32, 8)>>>(Wq, Wk, Wv, Wo);

    // QKV projections (merged, head-major out)
    mm_nt<128,1><<<dim3(8,16,3),256,SM128>>>(hs,1024,0, WtQ,WtK,WtV, 1024,0,0,
                                             Q_,K_,V_, 0,0, 1024, bq,bk,bv, nullptr, SS);
    transpose_v<<<dim3(32, 2, 32), dim3(32, 8)>>>();

    // position projections (merged)
    mm_nt<128,1><<<dim3(8,4,2),256,SM128>>>(rel,1024,0, WtK,WtQ,nullptr, 1024,0,0,
                                            PK_,PQ_,nullptr, 0,0, 1024, bk,bq,nullptr, nullptr, PP);

    // C2P[bh][q][p] = Q @ posK^T   (B indexed z&15)
    mm_nt<128,0><<<dim3(4,8,32),256,SM128>>>(Q_,64,(long long)SS*DD, PK_,nullptr,nullptr,
                                             64,(long long)PP*DD, 1,
                                             C2P_,nullptr,nullptr, PP,(long long)SS*PP, 64,
                                             nullptr,nullptr,nullptr, nullptr, 0);
    // P2Ct[bh][p][k] = posQ @ K^T  (A indexed z&15)  -- transposed layout!
    mm_nt<128,0><<<dim3(8,4,32),256,SM128>>>(PQ_,64,(long long)PP*DD, K_,nullptr,nullptr,
                                             64,(long long)SS*DD, 2,
                                             P2CT_,nullptr,nullptr, SS,(long long)PP*SS, 64,
                                             nullptr,nullptr,nullptr, nullptr, 0);

    // scores = (Q K^T + c2p gather)*scale, masked -> -3e38
    mm_nt<128,3><<<dim3(8,8,32),256,SM128>>>(Q_,64,(long long)SS*DD, K_,nullptr,nullptr,
                                             64,(long long)SS*DD, 0,
                                             S_,nullptr,nullptr, SS,(long long)SS*SS, 64,
                                             nullptr,nullptr,nullptr, (const float*)am, 0);

    // fused p2c-bias + softmax + PV
    softpv_kernel<<<dim3(8, 32), 256, SP_TOTAL>>>();

    // output projection + residual, then layernorm
    mm_nt<128,2><<<dim3(8,16,1),256,SM128>>>(CTX_,1024,0, WtO,nullptr,nullptr, 1024,0,0,
                                             Hb_,nullptr,nullptr, 1024,0, 1024,
                                             bo,nullptr,nullptr, hs, 0);
    ln_kernel<<<BB*SS, 256>>>(lw, lb, out);
}

// round 7
// speedup vs baseline: 1.3857x; 1.0256x over previous
#include <cuda_runtime.h>
#include <math.h>
#include <stdint.h>

#define BB 2
#define SS 1024
#define DMODEL 1024
#define HH 16
#define DD 64
#define PP 512               // 2*SPAN
#define BH (BB*HH)
#define INV_SCALE 0.07216878364870323f   // 1/sqrt(192)
#define STAGES 3

// ---------------- scratch (static device memory; no allocs allowed) ----------
__device__ float g_Q[BH*SS*DD];      // [bh][s][64]
__device__ float g_K[BH*SS*DD];
__device__ float g_V[BH*SS*DD];
__device__ float g_Vt[BH*DD*SS];     // [bh][64][s]
__device__ float g_posK[HH*PP*DD];   // [h][p][64]
__device__ float g_posQ[HH*PP*DD];
__device__ float g_Wt[4u*DMODEL*DMODEL]; // Wq^T, Wk^T, Wv^T, Wo^T
__device__ float g_C2P[(size_t)BH*SS*PP];   // [bh][q][p]
__device__ float g_P2C[(size_t)BH*SS*PP];   // [bh][k][p]
__device__ float g_S[(size_t)BH*SS*SS];
__device__ float g_ctx[BB*SS*DMODEL];
__device__ float g_H[BB*SS*DMODEL];
__device__ int   g_idx[2047];

// ---------------- idx table: clip(bucket(delta)+256, 0, 511) -----------------
__global__ void build_idx_kernel() {
    int t = blockIdx.x * blockDim.x + threadIdx.x;
    if (t >= 2047) return;
    int rel = t - 1023;
    int bucket;
    if (rel > -128 && rel < 128) {
        bucket = rel;
    } else {
        double abs_pos = fabs((double)rel);
        if (abs_pos <= 128.0) {
            bucket = rel;
        } else {
            int sgn = (rel > 0) - (rel < 0);
            double lp = ceil(log(abs_pos / 128.0) / log(511.0 / 128.0) * 127.0) + 128.0;
            bucket = (int)lp * sgn;
        }
    }
    int i1 = bucket + 256;
    i1 = i1 < 0 ? 0 : (i1 > 511 ? 511 : i1);
    g_idx[t] = i1;
}

__device__ __forceinline__ float to_tf32(float x) {
    float y;
    asm("cvt.rna.tf32.f32 %0, %1;" : "=f"(y) : "f"(x));
    return y;
}

__device__ __forceinline__ void mma_tf32(float (&d)[4],
                                         uint32_t a0, uint32_t a1, uint32_t a2, uint32_t a3,
                                         uint32_t b0, uint32_t b1) {
    asm volatile(
        "mma.sync.aligned.m16n8k8.row.col.f32.tf32.tf32.f32 "
        "{%0,%1,%2,%3}, {%4,%5,%6,%7}, {%8,%9}, {%0,%1,%2,%3};\n"
        : "+f"(d[0]), "+f"(d[1]), "+f"(d[2]), "+f"(d[3])
        : "r"(a0), "r"(a1), "r"(a2), "r"(a3), "r"(b0), "r"(b1));
}

__device__ __forceinline__ void cpa16(uint32_t s, const float* g) {
    asm volatile("cp.async.cg.shared.global [%0], [%1], 16;\n" :: "r"(s), "l"(g));
}
#define CP_COMMIT() asm volatile("cp.async.commit_group;\n" ::: "memory")
#define CP_WAIT1()  asm volatile("cp.async.wait_group 1;\n" ::: "memory")
#define CP_WAIT0()  asm volatile("cp.async.wait_group 0;\n" ::: "memory")

// ============================================================================
// NT tf32 GEMM, 3-stage cp.async pipeline, XOR-swizzled smem.
//   C[z] = A[z] (MxK row-major) @ B[z] (NxK row-major)^T + epilogue
// mods: bit0 -> B index z&15 ; bit1 -> A index z&15
// EPI 0: plain store   EPI 1: head-major scatter + bias (z selects B/bias/O)
// EPI 2: +bias+resid   EPI 3: scores = (QK + c2p + p2c gathers)*scale,
//                              masked -> -3e38  (resid param = mask pointer)
// ============================================================================
template<int BN, int EPI>
__global__ __launch_bounds__(256) void mm_nt(
    const float* __restrict__ A, int lda, long long sAz,
    const float* __restrict__ B0, const float* __restrict__ B1, const float* __restrict__ B2,
    int ldb, long long sBz, int mods,
    float* __restrict__ O0, float* __restrict__ O1, float* __restrict__ O2,
    int ldc, long long sCz, int K,
    const float* __restrict__ bias0, const float* __restrict__ bias1, const float* __restrict__ bias2,
    const float* __restrict__ resid, int srows)
{
    constexpr int WN8 = BN / 32;
    constexpr int AF = 128 * 32;
    constexpr int BF = BN * 32;
    extern __shared__ float sm[];
    float* sA = sm;
    float* sB = sm + STAGES * AF;

    const int z = blockIdx.z;
    const float* Bsel = B0; const float* bias = bias0; float* Osel = O0;
    if (EPI == 1) {
        if (z == 1)      { Bsel = B1; bias = bias1; Osel = O1; }
        else if (z == 2) { Bsel = B2; bias = bias2; Osel = O2; }
    }
    const float* Ag = A + (size_t)((mods & 2) ? (z & 15) : z) * sAz;
    const float* Bg = Bsel + (size_t)((mods & 1) ? (z & 15) : z) * sBz;

    const int tid = threadIdx.x;
    const int m0 = blockIdx.y * 128, n0 = blockIdx.x * BN;
    const uint32_t sA_u = (uint32_t)__cvta_generic_to_shared(sA);
    const uint32_t sB_u = (uint32_t)__cvta_generic_to_shared(sB);

    const int wid = tid >> 5, lane = tid & 31;
    const int wm = wid & 1, wn = wid >> 1;
    const int r = lane >> 2, cq = lane & 3;

    float acc[4][WN8][4];
    #pragma unroll
    for (int mt = 0; mt < 4; mt++)
        #pragma unroll
        for (int nt = 0; nt < WN8; nt++)
            #pragma unroll
            for (int q = 0; q < 4; q++) acc[mt][nt][q] = 0.f;

    auto loadStage = [&](int st, int k0) {
        #pragma unroll
        for (int i = 0; i < 4; i++) {
            int id = tid + i * 256;
            int row = id >> 3, c = id & 7;
            uint32_t dst = sA_u + (uint32_t)((st * AF + row * 32 + ((c ^ (row & 7)) << 2)) << 2);
            cpa16(dst, Ag + (size_t)(m0 + row) * lda + k0 + (c << 2));
        }
        #pragma unroll
        for (int i = 0; i < BN / 32; i++) {
            int id = tid + i * 256;
            int row = id >> 3, c = id & 7;
            uint32_t dst = sB_u + (uint32_t)((st * BF + row * 32 + ((c ^ (row & 7)) << 2)) << 2);
            cpa16(dst, Bg + (size_t)(n0 + row) * ldb + k0 + (c << 2));
        }
    };

    const int nk = K >> 5;
    loadStage(0, 0);  CP_COMMIT();
    loadStage(1, 32); CP_COMMIT();

    for (int it = 0; it < nk; it++) {
        CP_WAIT1();
        __syncthreads();
        int nxt = it + 2;
        if (nxt < nk) loadStage(nxt % STAGES, nxt * 32);
        CP_COMMIT();

        const float* a = sA + (it % STAGES) * AF;
        const float* b = sB + (it % STAGES) * BF;
        #pragma unroll
        for (int ks = 0; ks < 4; ks++) {
            uint32_t af0[4], af1[4], af2[4], af3[4];
            #pragma unroll
            for (int mt = 0; mt < 4; mt++) {
                int R = wm * 64 + mt * 16 + r;
                int r7 = R & 7;
                int lo = ((2 * ks) ^ r7) << 2, hi = ((2 * ks + 1) ^ r7) << 2;
                af0[mt] = __float_as_uint(a[R * 32 + lo + cq]);
                af2[mt] = __float_as_uint(a[R * 32 + hi + cq]);
                af1[mt] = __float_as_uint(a[(R + 8) * 32 + lo + cq]);
                af3[mt] = __float_as_uint(a[(R + 8) * 32 + hi + cq]);
            }
            #pragma unroll
            for (int nt = 0; nt < WN8; nt++) {
                int Nn = wn * WN8 * 8 + nt * 8 + r;
                int n7 = Nn & 7;
                int lo = ((2 * ks) ^ n7) << 2, hi = ((2 * ks + 1) ^ n7) << 2;
                uint32_t b0 = __float_as_uint(b[Nn * 32 + lo + cq]);
                uint32_t b1 = __float_as_uint(b[Nn * 32 + hi + cq]);
                #pragma unroll
                for (int mt = 0; mt < 4; mt++)
                    mma_tf32(acc[mt][nt], af0[mt], af1[mt], af2[mt], af3[mt], b0, b1);
            }
        }
        __syncthreads();
    }

    float* Cz = Osel + (size_t)z * sCz;
    #pragma unroll
    for (int mt = 0; mt < 4; mt++) {
        #pragma unroll
        for (int e = 0; e < 2; e++) {
            int gm = m0 + wm * 64 + mt * 16 + r + e * 8;
            #pragma unroll
            for (int nt = 0; nt < WN8; nt++) {
                int gn = n0 + wn * WN8 * 8 + nt * 8 + 2 * cq;
                float v0 = acc[mt][nt][e * 2 + 0];
                float v1 = acc[mt][nt][e * 2 + 1];
                if (EPI == 0) {
                    float2 o = {v0, v1};
                    *(float2*)(Cz + (size_t)gm * ldc + gn) = o;
                } else if (EPI == 1) {
                    int h = gn >> 6, d = gn & 63;
                    int b = gm / srows, s = gm % srows;
                    float2 o = {v0 + bias[gn], v1 + bias[gn + 1]};
                    *(float2*)(Osel + ((((size_t)b * HH + h) * srows + s) << 6) + d) = o;
                } else if (EPI == 2) {
                    size_t ad = (size_t)gm * ldc + gn;
                    float2 rr = *(const float2*)(resid + ad);
                    float2 o = {v0 + bias[gn] + rr.x, v1 + bias[gn + 1] + rr.y};
                    *(float2*)(Osel + ad) = o;
                } else if (EPI == 3) {
                    int id0 = g_idx[gm - gn + 1023];
                    int id1 = g_idx[gm - gn + 1022];
                    size_t cb = ((size_t)z * SS + gm) * PP;
                    const int* amr = (const int*)resid + ((size_t)((z >> 4) * SS + gm)) * SS;
                    int2 mk = *(const int2*)(amr + gn);
                    float o0 = mk.x ? (v0 + g_C2P[cb + id0]
                                       + g_P2C[((size_t)z * SS + gn) * PP + id0]) * INV_SCALE
                                    : -3.0e38f;
                    float o1 = mk.y ? (v1 + g_C2P[cb + id1]
                                       + g_P2C[((size_t)z * SS + gn + 1) * PP + id1]) * INV_SCALE
                                    : -3.0e38f;
                    float2 o = {o0, o1};
                    *(float2*)(Cz + (size_t)gm * ldc + gn) = o;
                }
            }
        }
    }
}

// -------- weight transpose (with tf32 rounding): Wt[n][k] = tf32(W[k][n]) ----
__global__ void transpose_w(const float* __restrict__ W0, const float* __restrict__ W1,
                            const float* __restrict__ W2, const float* __restrict__ W3)
{
    __shared__ float t[32][33];
    int zz = blockIdx.z;
    const float* W = zz == 0 ? W0 : zz == 1 ? W1 : zz == 2 ? W2 : W3;
    float* Tz = g_Wt + (size_t)zz * DMODEL * DMODEL;
    int x = blockIdx.x * 32 + threadIdx.x;
    int y0 = blockIdx.y * 32;
    #pragma unroll
    for (int i = threadIdx.y; i < 32; i += 8)
        t[i][threadIdx.x] = to_tf32(W[(size_t)(y0 + i) * DMODEL + x]);
    __syncthreads();
    int xo = blockIdx.y * 32 + threadIdx.x;
    int yo0 = blockIdx.x * 32;
    #pragma unroll
    for (int i = threadIdx.y; i < 32; i += 8)
        Tz[(size_t)(yo0 + i) * DMODEL + xo] = t[threadIdx.x][i];
}

// -------- V transpose per head: Vt[bh][d][s] = V[bh][s][d] --------------------
__global__ void transpose_v()
{
    __shared__ float t[32][33];
    int bh = blockIdx.z;
    int s0 = blockIdx.x * 32, d0 = blockIdx.y * 32;
    const float* Vi = g_V + (size_t)bh * SS * DD;
    float* Vo = g_Vt + (size_t)bh * DD * SS;
    #pragma unroll
    for (int i = threadIdx.y; i < 32; i += 8)
        t[i][threadIdx.x] = Vi[(size_t)(s0 + i) * DD + d0 + threadIdx.x];
    __syncthreads();
    #pragma unroll
    for (int i = threadIdx.y; i < 32; i += 8)
        Vo[(size_t)(d0 + i) * SS + s0 + threadIdx.x] = t[threadIdx.x][i];
}

// ============================================================================
// Two-pass fused softmax + PV.  CTA = 64 q-rows of one bh.
// Pass 1: stream S tiles, row max only.  Pass 2: re-stream S (L2-hot), exp
// once into swizzled sP, accumulate l, mma P@V; normalize by 1/l at the end.
// smem: sS[2][64*64], sV[2][64*64], sP[64*64], redm[4*64], redl[4*64]
// ============================================================================
#define SP2_SV   8192
#define SP2_P    16384
#define SP2_RM   20480
#define SP2_RL   20736
#define SP2_TOTAL ((20992) * 4)

__global__ __launch_bounds__(256, 2) void softpv2_kernel()
{
    extern __shared__ float fs[];
    float* redm = fs + SP2_RM;
    float* redl = fs + SP2_RL;

    const int bh = blockIdx.y, b = bh >> 4, h = bh & 15;
    const int q0 = blockIdx.x * 64;
    const int tid = threadIdx.x;
    const int row4 = tid >> 2, cg = tid & 3;     // transform mapping: 4 thr/row
    const int wid = tid >> 5, lane = tid & 31;
    const int wm = wid & 1, wn = wid >> 1, r = lane >> 2, cq = lane & 3;

    const float* Sg = g_S + (size_t)bh * SS * SS + (size_t)q0 * SS;
    const float* Vg = g_Vt + (size_t)bh * DD * SS;
    const uint32_t smem_u = (uint32_t)__cvta_generic_to_shared(fs);

    auto loadS = [&](int st, int k0) {
        #pragma unroll
        for (int i = 0; i < 4; i++) {
            int id = tid + i * 256;
            int rr = id >> 4, c4 = (id & 15) << 2;
            uint32_t dst = smem_u + (uint32_t)((st * 4096 + rr * 64 + (((c4 >> 2) ^ (rr & 7)) << 2)) << 2);
            cpa16(dst, Sg + (size_t)rr * SS + k0 + c4);
        }
    };
    auto loadV = [&](int st, int k0) {
        #pragma unroll
        for (int i = 0; i < 4; i++) {
            int id = tid + i * 256;
            int rr = id >> 4, c4 = (id & 15) << 2;
            uint32_t dst = smem_u + (uint32_t)((SP2_SV + st * 4096 + rr * 64 + (((c4 >> 2) ^ (rr & 7)) << 2)) << 2);
            cpa16(dst, Vg + (size_t)rr * SS + k0 + c4);
        }
    };

    // ---------------- pass 1: row max ----------------
    loadS(0, 0);  CP_COMMIT();
    loadS(1, 64); CP_COMMIT();
    float mx = -3.0e38f;
    for (int it = 0; it < 16; it++) {
        CP_WAIT1();
        __syncthreads();
        const float* t = fs + (it & 1) * 4096;
        #pragma unroll
        for (int j = 0; j < 4; j++) {
            int c4 = cg * 16 + j * 4;
            float4 v = *(const float4*)&t[row4 * 64 + (((c4 >> 2) ^ (row4 & 7)) << 2)];
            mx = fmaxf(mx, fmaxf(fmaxf(v.x, v.y), fmaxf(v.z, v.w)));
        }
        __syncthreads();
        if (it + 2 < 16) loadS(it & 1, (it + 2) * 64);
        CP_COMMIT();
    }
    redm[cg * 64 + row4] = mx;
    __syncthreads();
    const float rowm = fmaxf(fmaxf(redm[row4], redm[64 + row4]),
                             fmaxf(redm[128 + row4], redm[192 + row4]));

    // ---------------- pass 2: exp + l + PV ----------------
    loadS(0, 0); loadV(0, 0); CP_COMMIT();
    loadS(1, 64); loadV(1, 64); CP_COMMIT();

    float lpart = 0.f;
    float acc[2][2][4];
    #pragma unroll
    for (int mt = 0; mt < 2; mt++)
        #pragma unroll
        for (int nt = 0; nt < 2; nt++)
            #pragma unroll
            for (int q = 0; q < 4; q++) acc[mt][nt][q] = 0.f;

    float* sP = fs + SP2_P;
    for (int it = 0; it < 16; it++) {
        CP_WAIT1();
        __syncthreads();
        const float* tS = fs + (it & 1) * 4096;
        const float* tV = fs + SP2_SV + (it & 1) * 4096;

        // transform: p = exp(s - rowm), sentinel -> 0
        #pragma unroll
        for (int j = 0; j < 4; j++) {
            int c4 = cg * 16 + j * 4;
            int ad = row4 * 64 + (((c4 >> 2) ^ (row4 & 7)) << 2);
            float4 v = *(const float4*)&tS[ad];
            float4 p;
            p.x = v.x < -1.0e37f ? 0.f : __expf(v.x - rowm);
            p.y = v.y < -1.0e37f ? 0.f : __expf(v.y - rowm);
            p.z = v.z < -1.0e37f ? 0.f : __expf(v.z - rowm);
            p.w = v.w < -1.0e37f ? 0.f : __expf(v.w - rowm);
            *(float4*)&sP[ad] = p;
            lpart += p.x + p.y + p.z + p.w;
        }
        __syncthreads();               // sP ready; tS fully consumed

        // PV mma: acc += P(64x64) @ V^T-tile(64x64)
        #pragma unroll
        for (int ks = 0; ks < 8; ks++) {
            uint32_t af0[2], af1[2], af2[2], af3[2];
            #pragma unroll
            for (int mt = 0; mt < 2; mt++) {
                int R = wm * 32 + mt * 16 + r;
                int r7 = R & 7;
                int lo = ((2 * ks) ^ r7) << 2, hi = ((2 * ks + 1) ^ r7) << 2;
                af0[mt] = __float_as_uint(sP[R * 64 + lo + cq]);
                af2[mt] = __float_as_uint(sP[R * 64 + hi + cq]);
                af1[mt] = __float_as_uint(sP[(R + 8) * 64 + lo + cq]);
                af3[mt] = __float_as_uint(sP[(R + 8) * 64 + hi + cq]);
            }
            #pragma unroll
            for (int nt = 0; nt < 2; nt++) {
                int n = wn * 16 + nt * 8 + r;   // d index
                int n7 = n & 7;
                uint32_t b0 = __float_as_uint(tV[n * 64 + (((2 * ks) ^ n7) << 2) + cq]);
                uint32_t b1 = __float_as_uint(tV[n * 64 + (((2 * ks + 1) ^ n7) << 2) + cq]);
                #pragma unroll
                for (int mt = 0; mt < 2; mt++)
                    mma_tf32(acc[mt][nt], af0[mt], af1[mt], af2[mt], af3[mt], b0, b1);
            }
        }
        __syncthreads();               // tS/tV free for refill
        if (it + 2 < 16) { loadS(it & 1, (it + 2) * 64); loadV(it & 1, (it + 2) * 64); }
        CP_COMMIT();
    }

    redl[cg * 64 + row4] = lpart;
    __syncthreads();

    // epilogue: normalize by 1/l, write ctx
    #pragma unroll
    for (int mt = 0; mt < 2; mt++) {
        #pragma unroll
        for (int e = 0; e < 2; e++) {
            int R = wm * 32 + mt * 16 + r + e * 8;
            float l = redl[R] + redl[64 + R] + redl[128 + R] + redl[192 + R];
            float inv = l > 0.f ? 1.f / l : 0.f;
            int qg = q0 + R;
            #pragma unroll
            for (int nt = 0; nt < 2; nt++) {
                int d = wn * 16 + nt * 8 + 2 * cq;
                float2 o = {acc[mt][nt][e * 2 + 0] * inv, acc[mt][nt][e * 2 + 1] * inv};
                *(float2*)(g_ctx + (size_t)(b * SS + qg) * DMODEL + h * DD + d) = o;
            }
        }
    }
}

// ---------------- layernorm of g_H, write to output --------------------------
__global__ __launch_bounds__(256) void ln_kernel(
    const float* __restrict__ lw, const float* __restrict__ lb,
    float* __restrict__ out)
{
    __shared__ float red[256];
    __shared__ float red2[256];
    int r = blockIdx.x, t = threadIdx.x;
    const float* x = g_H + (size_t)r * DMODEL;
    float s = 0.f, s2 = 0.f;
    #pragma unroll
    for (int i = 0; i < 4; i++) {
        float v = x[t + i * 256];
        s += v; s2 += v * v;
    }
    red[t] = s; red2[t] = s2; __syncthreads();
    for (int st = 128; st; st >>= 1) {
        if (t < st) { red[t] += red[t + st]; red2[t] += red2[t + st]; }
        __syncthreads();
    }
    float mu = red[0] * (1.f / DMODEL);
    float var = red2[0] * (1.f / DMODEL) - mu * mu;
    float inv = rsqrtf(var + 1e-7f);
    #pragma unroll
    for (int i = 0; i < 4; i++) {
        int c = t + i * 256;
        out[(size_t)r * DMODEL + c] = (x[c] - mu) * inv * lw[c] + lb[c];
    }
}

// ---------------- launch ------------------------------------------------------
extern "C" void kernel_launch(void* const* d_in, const int* in_sizes, int n_in,
                              void* d_out, int out_size)
{
    const float* hs  = (const float*)d_in[0];
    const float* rel = (const float*)d_in[1];
    const float* Wq  = (const float*)d_in[2];  const float* bq = (const float*)d_in[3];
    const float* Wk  = (const float*)d_in[4];  const float* bk = (const float*)d_in[5];
    const float* Wv  = (const float*)d_in[6];  const float* bv = (const float*)d_in[7];
    const float* Wo  = (const float*)d_in[8];  const float* bo = (const float*)d_in[9];
    const float* lw  = (const float*)d_in[10]; const float* lb = (const float*)d_in[11];
    const int*   am  = (const int*)d_in[12];
    float* out = (float*)d_out;

    float *Q_, *K_, *V_, *PK_, *PQ_, *WT_, *C2P_, *P2C_, *S_, *CTX_, *Hb_;
    cudaGetSymbolAddress((void**)&Q_,    g_Q);
    cudaGetSymbolAddress((void**)&K_,    g_K);
    cudaGetSymbolAddress((void**)&V_,    g_V);
    cudaGetSymbolAddress((void**)&PK_,   g_posK);
    cudaGetSymbolAddress((void**)&PQ_,   g_posQ);
    cudaGetSymbolAddress((void**)&WT_,   g_Wt);
    cudaGetSymbolAddress((void**)&C2P_,  g_C2P);
    cudaGetSymbolAddress((void**)&P2C_,  g_P2C);
    cudaGetSymbolAddress((void**)&S_,    g_S);
    cudaGetSymbolAddress((void**)&CTX_,  g_ctx);
    cudaGetSymbolAddress((void**)&Hb_,   g_H);

    const float* WtQ = WT_;
    const float* WtK = WT_ + (size_t)1 * DMODEL * DMODEL;
    const float* WtV = WT_ + (size_t)2 * DMODEL * DMODEL;
    const float* WtO = WT_ + (size_t)3 * DMODEL * DMODEL;

    const int SM128 = STAGES * (128 * 32 + 128 * 32) * 4;   // 98304
    cudaFuncSetAttribute(mm_nt<128,0>, cudaFuncAttributeMaxDynamicSharedMemorySize, SM128);
    cudaFuncSetAttribute(mm_nt<128,1>, cudaFuncAttributeMaxDynamicSharedMemorySize, SM128);
    cudaFuncSetAttribute(mm_nt<128,2>, cudaFuncAttributeMaxDynamicSharedMemorySize, SM128);
    cudaFuncSetAttribute(mm_nt<128,3>, cudaFuncAttributeMaxDynamicSharedMemorySize, SM128);
    cudaFuncSetAttribute(softpv2_kernel, cudaFuncAttributeMaxDynamicSharedMemorySize, SP2_TOTAL);

    build_idx_kernel<<<8, 256>>>();
    transpose_w<<<dim3(32, 32, 4), dim3(32, 8)>>>(Wq, Wk, Wv, Wo);

    // QKV projections (merged, head-major out)
    mm_nt<128,1><<<dim3(8,16,3),256,SM128>>>(hs,1024,0, WtQ,WtK,WtV, 1024,0,0,
                                             Q_,K_,V_, 0,0, 1024, bq,bk,bv, nullptr, SS);
    transpose_v<<<dim3(32, 2, 32), dim3(32, 8)>>>();

    // position projections (merged)
    mm_nt<128,1><<<dim3(8,4,2),256,SM128>>>(rel,1024,0, WtK,WtQ,nullptr, 1024,0,0,
                                            PK_,PQ_,nullptr, 0,0, 1024, bk,bq,nullptr, nullptr, PP);

    // C2P[bh][q][p] = Q @ posK^T   (B indexed z&15)
    mm_nt<128,0><<<dim3(4,8,32),256,SM128>>>(Q_,64,(long long)SS*DD, PK_,nullptr,nullptr,
                                             64,(long long)PP*DD, 1,
                                             C2P_,nullptr,nullptr, PP,(long long)SS*PP, 64,
                                             nullptr,nullptr,nullptr, nullptr, 0);
    // P2C[bh][k][p] = K @ posQ^T   (B indexed z&15)
    mm_nt<128,0><<<dim3(4,8,32),256,SM128>>>(K_,64,(long long)SS*DD, PQ_,nullptr,nullptr,
                                             64,(long long)PP*DD, 1,
                                             P2C_,nullptr,nullptr, PP,(long long)SS*PP, 64,
                                             nullptr,nullptr,nullptr, nullptr, 0);

    // scores = (Q K^T + c2p + p2c gathers)*scale, masked -> -3e38
    mm_nt<128,3><<<dim3(8,8,32),256,SM128>>>(Q_,64,(long long)SS*DD, K_,nullptr,nullptr,
                                             64,(long long)SS*DD, 0,
                                             S_,nullptr,nullptr, SS,(long long)SS*SS, 64,
                                             nullptr,nullptr,nullptr, (const float*)am, 0);

    // fused two-pass softmax + PV
    softpv2_kernel<<<dim3(16, 32), 256, SP2_TOTAL>>>();

    // output projection + residual, then layernorm
    mm_nt<128,2><<<dim3(8,16,1),256,SM128>>>(CTX_,1024,0, WtO,nullptr,nullptr, 1024,0,0,
                                             Hb_,nullptr,nullptr, 1024,0, 1024,
                                             bo,nullptr,nullptr, hs, 0);
    ln_kernel<<<BB*SS, 256>>>(lw, lb, out);
}